// round 1
// baseline (speedup 1.0000x reference)
#include <cuda_runtime.h>

// ---------------------------------------------------------------------------
// MHA: out = softmax((qWq)(qWk)^T / sqrt(64)) (qWv) Wo + biases
// b=2, s=2048, dim=1024, 16 heads x 64
// Round 1: fp32 baseline. 4x SGEMM (64x64x16 tiles, 4x4 microtile) +
// flash-attention style fused softmax-attention kernel.
// ---------------------------------------------------------------------------

#define SEQ     2048
#define BATCH   2
#define NH      16
#define HD      64
#define HID     1024
#define MROWS   (BATCH * SEQ)   // 4096

// Scratch (allocation-free rule: __device__ globals)
__device__ float g_Q[MROWS * HID];
__device__ float g_K[MROWS * HID];
__device__ float g_V[MROWS * HID];
__device__ float g_O[MROWS * HID];

// ---------------------------------------------------------------------------
// SGEMM with bias: C[M,N] = A[M,K] @ B[K,N] + bias[N]
// Block tile 64x64, K-tile 16, 256 threads, 4x4 per-thread microtile.
// M,N multiples of 64; K multiple of 16 (true for all launches here).
// ---------------------------------------------------------------------------
__global__ __launch_bounds__(256) void gemm_bias_kernel(
    const float* __restrict__ A, int lda,
    const float* __restrict__ B, int ldb,
    const float* __restrict__ bias,
    float* __restrict__ C, int ldc,
    int K)
{
    __shared__ float As[16][68];   // transposed A tile [k][m], padded
    __shared__ float Bs[16][64];   // B tile [k][n]

    const int tid  = threadIdx.x;
    const int tx   = tid & 15;          // 0..15 -> N micro
    const int ty   = tid >> 4;          // 0..15 -> M micro
    const int row0 = blockIdx.y * 64;
    const int col0 = blockIdx.x * 64;

    // load mapping
    const int a_row = tid >> 2;           // 0..63
    const int a_col = (tid & 3) << 2;     // 0,4,8,12
    const int b_row = tid >> 4;           // 0..15
    const int b_col = (tid & 15) << 2;    // 0..60

    const float* Aptr = A + (size_t)(row0 + a_row) * lda + a_col;
    const float* Bptr = B + (size_t)b_row * ldb + col0 + b_col;

    float acc[4][4] = {};

    for (int k0 = 0; k0 < K; k0 += 16) {
        float4 av = *(const float4*)(Aptr + k0);
        float4 bv = *(const float4*)(Bptr + (size_t)k0 * ldb);
        __syncthreads();
        As[a_col + 0][a_row] = av.x;
        As[a_col + 1][a_row] = av.y;
        As[a_col + 2][a_row] = av.z;
        As[a_col + 3][a_row] = av.w;
        *(float4*)&Bs[b_row][b_col] = bv;
        __syncthreads();

        #pragma unroll
        for (int k = 0; k < 16; k++) {
            float a[4], b[4];
            *(float4*)a = *(const float4*)&As[k][ty * 4];
            *(float4*)b = *(const float4*)&Bs[k][tx * 4];
            #pragma unroll
            for (int ii = 0; ii < 4; ii++)
                #pragma unroll
                for (int jj = 0; jj < 4; jj++)
                    acc[ii][jj] += a[ii] * b[jj];
        }
    }

    float4 bb = *(const float4*)&bias[col0 + tx * 4];
    const float bba[4] = {bb.x, bb.y, bb.z, bb.w};
    #pragma unroll
    for (int ii = 0; ii < 4; ii++) {
        float4 o;
        o.x = acc[ii][0] + bba[0];
        o.y = acc[ii][1] + bba[1];
        o.z = acc[ii][2] + bba[2];
        o.w = acc[ii][3] + bba[3];
        *(float4*)&C[(size_t)(row0 + ty * 4 + ii) * ldc + col0 + tx * 4] = o;
    }
}

// ---------------------------------------------------------------------------
// Fused attention: per block = (q-tile of 64 rows, head, batch).
// Online softmax over kv tiles of 64. S and O phases are both register-tiled
// GEMMs through shared memory (Q^T, K^T, P^T staged transposed; V natural).
// Layout: Q/K/V are [b, s, h*64+d] fp32 (head-contiguous), output same.
// ---------------------------------------------------------------------------
#define ATTN_SMEM_FLOATS (64*64 + 64*68 + 64*64 + 64*68)   // Qst,Kst,Vs,Pst

__global__ __launch_bounds__(256) void attn_kernel(
    const float* __restrict__ Q,
    const float* __restrict__ K,
    const float* __restrict__ V,
    float* __restrict__ O)
{
    extern __shared__ float sm[];
    float* Qst = sm;                    // [d][i]  64x64
    float* Kst = Qst + 64 * 64;         // [d][j]  64x68 (padded)
    float* Vs  = Kst + 64 * 68;         // [j][c]  64x64
    float* Pst = Vs  + 64 * 64;         // [j][i]  64x68 (padded)

    const int tid = threadIdx.x;
    const int tx  = tid & 15;           // column micro (j for S, c for O)
    const int ty  = tid >> 4;           // row micro (i)
    const int b   = blockIdx.z;
    const int h   = blockIdx.y;
    const int q0  = blockIdx.x * 64;
    const float scale = 0.125f;         // 64^-0.5

    const float* Qg = Q + ((size_t)b * SEQ + q0) * HID + h * HD;
    const float* Kg = K + (size_t)b * SEQ * HID + h * HD;
    const float* Vg = V + (size_t)b * SEQ * HID + h * HD;

    // Load Q tile transposed (once per block)
    for (int idx = tid; idx < 4096; idx += 256) {
        int r = idx >> 6, d = idx & 63;
        Qst[d * 64 + r] = Qg[(size_t)r * HID + d];
    }

    float m[4], l[4], acc[4][4];
    #pragma unroll
    for (int ii = 0; ii < 4; ii++) {
        m[ii] = -1e30f;
        l[ii] = 0.0f;
        #pragma unroll
        for (int jj = 0; jj < 4; jj++) acc[ii][jj] = 0.0f;
    }

    for (int kv0 = 0; kv0 < SEQ; kv0 += 64) {
        __syncthreads();   // previous iteration's consumers done
        // K tile transposed, V tile natural
        for (int idx = tid; idx < 4096; idx += 256) {
            int j = idx >> 6, d = idx & 63;
            Kst[d * 68 + j] = Kg[(size_t)(kv0 + j) * HID + d];
        }
        for (int idx = tid; idx < 1024; idx += 256) {
            int j = idx >> 4, c4 = (idx & 15) << 2;
            *(float4*)&Vs[j * 64 + c4] =
                *(const float4*)&Vg[(size_t)(kv0 + j) * HID + c4];
        }
        __syncthreads();

        // ---- S = (Q K^T) * scale : 4x4 per thread ----
        float s[4][4] = {};
        #pragma unroll 8
        for (int d = 0; d < 64; d++) {
            float a[4], bb[4];
            *(float4*)a  = *(const float4*)&Qst[d * 64 + ty * 4];
            *(float4*)bb = *(const float4*)&Kst[d * 68 + tx * 4];
            #pragma unroll
            for (int ii = 0; ii < 4; ii++)
                #pragma unroll
                for (int jj = 0; jj < 4; jj++)
                    s[ii][jj] += a[ii] * bb[jj];
        }

        // ---- online softmax (row groups = 16 threads sharing ty) ----
        #pragma unroll
        for (int ii = 0; ii < 4; ii++) {
            #pragma unroll
            for (int jj = 0; jj < 4; jj++) s[ii][jj] *= scale;

            float mt = fmaxf(fmaxf(s[ii][0], s[ii][1]),
                             fmaxf(s[ii][2], s[ii][3]));
            mt = fmaxf(mt, __shfl_xor_sync(0xffffffffu, mt, 1));
            mt = fmaxf(mt, __shfl_xor_sync(0xffffffffu, mt, 2));
            mt = fmaxf(mt, __shfl_xor_sync(0xffffffffu, mt, 4));
            mt = fmaxf(mt, __shfl_xor_sync(0xffffffffu, mt, 8));

            float mn    = fmaxf(m[ii], mt);
            float alpha = __expf(m[ii] - mn);
            float ps = 0.0f;
            #pragma unroll
            for (int jj = 0; jj < 4; jj++) {
                s[ii][jj] = __expf(s[ii][jj] - mn);
                ps += s[ii][jj];
            }
            ps += __shfl_xor_sync(0xffffffffu, ps, 1);
            ps += __shfl_xor_sync(0xffffffffu, ps, 2);
            ps += __shfl_xor_sync(0xffffffffu, ps, 4);
            ps += __shfl_xor_sync(0xffffffffu, ps, 8);

            l[ii] = l[ii] * alpha + ps;
            m[ii] = mn;
            #pragma unroll
            for (int jj = 0; jj < 4; jj++) acc[ii][jj] *= alpha;
        }

        // ---- stage P^T (columns i of Pst touched only by this warp) ----
        __syncwarp();
        #pragma unroll
        for (int ii = 0; ii < 4; ii++)
            #pragma unroll
            for (int jj = 0; jj < 4; jj++)
                Pst[(tx * 4 + jj) * 68 + ty * 4 + ii] = s[ii][jj];
        __syncwarp();

        // ---- O += P V : 4x4 per thread ----
        #pragma unroll 8
        for (int j = 0; j < 64; j++) {
            float a[4], bb[4];
            *(float4*)a  = *(const float4*)&Pst[j * 68 + ty * 4];
            *(float4*)bb = *(const float4*)&Vs[j * 64 + tx * 4];
            #pragma unroll
            for (int ii = 0; ii < 4; ii++)
                #pragma unroll
                for (int jj = 0; jj < 4; jj++)
                    acc[ii][jj] += a[ii] * bb[jj];
        }
    }

    // epilogue: divide by l, write [b, q, h*64+c]
    float* Og = O + ((size_t)b * SEQ + q0) * HID + h * HD;
    #pragma unroll
    for (int ii = 0; ii < 4; ii++) {
        float inv = 1.0f / l[ii];
        float4 o;
        o.x = acc[ii][0] * inv;
        o.y = acc[ii][1] * inv;
        o.z = acc[ii][2] * inv;
        o.w = acc[ii][3] * inv;
        *(float4*)&Og[(size_t)(ty * 4 + ii) * HID + tx * 4] = o;
    }
}

// ---------------------------------------------------------------------------

extern "C" void kernel_launch(void* const* d_in, const int* in_sizes, int n_in,
                              void* d_out, int out_size)
{
    const float* q   = (const float*)d_in[0];   // [2,2048,1024]
    const float* Wq  = (const float*)d_in[1];   // [1024,1024]
    const float* bq  = (const float*)d_in[2];   // [1024]
    const float* Wkv = (const float*)d_in[3];   // [1024,2048]
    const float* bkv = (const float*)d_in[4];   // [2048]
    const float* Wo  = (const float*)d_in[5];   // [1024,1024]
    const float* bo  = (const float*)d_in[6];   // [1024]
    float* out = (float*)d_out;                 // [2,2048,1024]

    void *pQ, *pK, *pV, *pO;
    cudaGetSymbolAddress(&pQ, g_Q);
    cudaGetSymbolAddress(&pK, g_K);
    cudaGetSymbolAddress(&pV, g_V);
    cudaGetSymbolAddress(&pO, g_O);
    float* gQ = (float*)pQ;
    float* gK = (float*)pK;
    float* gV = (float*)pV;
    float* gO = (float*)pO;

    static bool attr_set = false;
    if (!attr_set) {
        cudaFuncSetAttribute(attn_kernel,
                             cudaFuncAttributeMaxDynamicSharedMemorySize,
                             ATTN_SMEM_FLOATS * (int)sizeof(float));
        attr_set = true;
    }

    dim3 blk(256);
    dim3 grid_proj(HID / 64, MROWS / 64);   // (16, 64)

    // Q = q @ Wq + bq
    gemm_bias_kernel<<<grid_proj, blk>>>(q, HID, Wq, HID, bq, gQ, HID, HID);
    // K = q @ Wkv[:, :1024] + bkv[:1024]
    gemm_bias_kernel<<<grid_proj, blk>>>(q, HID, Wkv, 2 * HID, bkv, gK, HID, HID);
    // V = q @ Wkv[:, 1024:] + bkv[1024:]
    gemm_bias_kernel<<<grid_proj, blk>>>(q, HID, Wkv + HID, 2 * HID, bkv + HID,
                                         gV, HID, HID);

    // attention
    dim3 grid_attn(SEQ / 64, NH, BATCH);    // (32, 16, 2)
    attn_kernel<<<grid_attn, blk, ATTN_SMEM_FLOATS * sizeof(float)>>>(gQ, gK, gV, gO);

    // out = O @ Wo + bo
    gemm_bias_kernel<<<grid_proj, blk>>>(gO, HID, Wo, HID, bo, out, HID, HID);
}

// round 3
// speedup vs baseline: 2.5799x; 2.5799x over previous
#include <cuda_runtime.h>
#include <cstdint>

// ---------------------------------------------------------------------------
// MHA: out = softmax((qWq)(qWk)^T / 8) (qWv) Wo + biases
// b=2, s=2048, dim=1024, 16 heads x 64
// R3: everything on mma.sync m16n8k8 tf32 (sm_103 baseline ISA; tcgen05 is
//     unavailable because the harness compiles PTX at compute_103, not 103a).
// ---------------------------------------------------------------------------

#define SEQ     2048
#define BATCH   2
#define NH      16
#define HD      64
#define HID     1024
#define MROWS   (BATCH * SEQ)   // 4096

__device__ float g_Q[MROWS * HID];
__device__ float g_K[MROWS * HID];
__device__ float g_V[MROWS * HID];
__device__ float g_O[MROWS * HID];

// ------------------------------ helpers ------------------------------------
__device__ __forceinline__ float tf32r(float f) {
    uint32_t r;
    asm("cvt.rna.tf32.f32 %0, %1;" : "=r"(r) : "f"(f));
    return __uint_as_float(r);
}

__device__ __forceinline__ void mma_tf32(float* d, const uint32_t* a,
                                         uint32_t b0, uint32_t b1) {
    asm volatile(
        "mma.sync.aligned.m16n8k8.row.col.f32.tf32.tf32.f32 "
        "{%0,%1,%2,%3}, {%4,%5,%6,%7}, {%8,%9}, {%0,%1,%2,%3};"
        : "+f"(d[0]), "+f"(d[1]), "+f"(d[2]), "+f"(d[3])
        : "r"(a[0]), "r"(a[1]), "r"(a[2]), "r"(a[3]), "r"(b0), "r"(b1));
}

// ============================ tf32 GEMM ====================================
// C[M,N] = A[M,K] @ B[K,N] + bias[N].  Tiles 128x128x32, 8 warps (2x4),
// warp tile 64x32 (4 mtiles x 4 ntiles of m16n8).  Double-buffered SMEM.
#define PADA 36
#define PADB 136
#define GEMM_SMEM ((2 * (128 * PADA + 32 * PADB)) * (int)sizeof(float))

__global__ __launch_bounds__(256) void gemm_tc(
    const float* __restrict__ A, int lda,
    const float* __restrict__ B, int ldb,
    const float* __restrict__ bias,
    float* __restrict__ C, int ldc, int K)
{
    extern __shared__ float smg[];
    float* As = smg;                     // [2][128*PADA]
    float* Bs = smg + 2 * 128 * PADA;    // [2][32*PADB]

    const int tid  = threadIdx.x;
    const int wid  = tid >> 5, lane = tid & 31;
    const int g    = lane >> 2, t = lane & 3;
    const int wr   = wid & 1,  wc = wid >> 1;
    const int row0 = blockIdx.y * 128;
    const int col0 = blockIdx.x * 128;

    const int ar = tid >> 3, ac = (tid & 7) * 4;   // A loads: rows ar+32i
    const int br = tid >> 3, bc = (tid & 7) * 4;   // B loads: row br, cols bc+32j

    const float* Ag = A + (size_t)row0 * lda;
    const float* Bg = B + col0;

    float4 ra[4], rb[4];
    const int NT = K >> 5;

    // prologue: load + stage ktile 0
    #pragma unroll
    for (int i = 0; i < 4; i++)
        ra[i] = *(const float4*)(Ag + (size_t)(ar + 32 * i) * lda + ac);
    #pragma unroll
    for (int j = 0; j < 4; j++)
        rb[j] = *(const float4*)(Bg + (size_t)br * ldb + bc + 32 * j);
    {
        float* Ad = As;
        float* Bd = Bs;
        #pragma unroll
        for (int i = 0; i < 4; i++) {
            float* d = Ad + (ar + 32 * i) * PADA + ac;
            d[0] = tf32r(ra[i].x); d[1] = tf32r(ra[i].y);
            d[2] = tf32r(ra[i].z); d[3] = tf32r(ra[i].w);
        }
        #pragma unroll
        for (int j = 0; j < 4; j++) {
            float* d = Bd + br * PADB + bc + 32 * j;
            d[0] = tf32r(rb[j].x); d[1] = tf32r(rb[j].y);
            d[2] = tf32r(rb[j].z); d[3] = tf32r(rb[j].w);
        }
    }
    __syncthreads();

    float acc[4][4][4] = {};

    for (int kt = 0; kt < NT; kt++) {
        // prefetch next ktile into registers
        if (kt + 1 < NT) {
            const int k0 = (kt + 1) * 32;
            #pragma unroll
            for (int i = 0; i < 4; i++)
                ra[i] = *(const float4*)(Ag + (size_t)(ar + 32 * i) * lda + k0 + ac);
            #pragma unroll
            for (int j = 0; j < 4; j++)
                rb[j] = *(const float4*)(Bg + (size_t)(k0 + br) * ldb + bc + 32 * j);
        }

        const float* Ac = As + (kt & 1) * 128 * PADA;
        const float* Bc = Bs + (kt & 1) * 32 * PADB;

        #pragma unroll
        for (int kk = 0; kk < 4; kk++) {
            uint32_t af[4][4];
            #pragma unroll
            for (int mt = 0; mt < 4; mt++) {
                const float* ap = Ac + (wr * 64 + mt * 16) * PADA + kk * 8;
                af[mt][0] = __float_as_uint(ap[ g      * PADA + t    ]);
                af[mt][1] = __float_as_uint(ap[(g + 8) * PADA + t    ]);
                af[mt][2] = __float_as_uint(ap[ g      * PADA + t + 4]);
                af[mt][3] = __float_as_uint(ap[(g + 8) * PADA + t + 4]);
            }
            #pragma unroll
            for (int nt = 0; nt < 4; nt++) {
                const float* bp = Bc + kk * 8 * PADB + wc * 32 + nt * 8 + g;
                uint32_t b0 = __float_as_uint(bp[ t      * PADB]);
                uint32_t b1 = __float_as_uint(bp[(t + 4) * PADB]);
                #pragma unroll
                for (int mt = 0; mt < 4; mt++)
                    mma_tf32(acc[mt][nt], af[mt], b0, b1);
            }
        }

        if (kt + 1 < NT) {
            __syncthreads();
            float* Ad = As + ((kt + 1) & 1) * 128 * PADA;
            float* Bd = Bs + ((kt + 1) & 1) * 32 * PADB;
            #pragma unroll
            for (int i = 0; i < 4; i++) {
                float* d = Ad + (ar + 32 * i) * PADA + ac;
                d[0] = tf32r(ra[i].x); d[1] = tf32r(ra[i].y);
                d[2] = tf32r(ra[i].z); d[3] = tf32r(ra[i].w);
            }
            #pragma unroll
            for (int j = 0; j < 4; j++) {
                float* d = Bd + br * PADB + bc + 32 * j;
                d[0] = tf32r(rb[j].x); d[1] = tf32r(rb[j].y);
                d[2] = tf32r(rb[j].z); d[3] = tf32r(rb[j].w);
            }
            __syncthreads();
        }
    }

    // epilogue
    #pragma unroll
    for (int mt = 0; mt < 4; mt++) {
        const int row = row0 + wr * 64 + mt * 16 + g;
        #pragma unroll
        for (int nt = 0; nt < 4; nt++) {
            const int col = col0 + wc * 32 + nt * 8 + 2 * t;
            float2 bb = *(const float2*)&bias[col];
            float2 v0 = {acc[mt][nt][0] + bb.x, acc[mt][nt][1] + bb.y};
            float2 v1 = {acc[mt][nt][2] + bb.x, acc[mt][nt][3] + bb.y};
            *(float2*)&C[(size_t)row * ldc + col]       = v0;
            *(float2*)&C[(size_t)(row + 8) * ldc + col] = v1;
        }
    }
}

// ============================ attention ====================================
// Per block: 128 q rows x (head, batch). 8 warps, warp w owns q rows
// [16w,16w+16). S = Q K^T and O += P V both on mma.sync tf32.
#define ATP 68
#define ATTN_SMEM ((2 * 64 * ATP + 128 * ATP) * (int)sizeof(float))

__global__ __launch_bounds__(256) void attn_tc(
    const float* __restrict__ Q,
    const float* __restrict__ Kin,
    const float* __restrict__ V,
    float* __restrict__ O)
{
    extern __shared__ float sma[];
    float* Ks = sma;                  // [j][d] 64xATP
    float* Vt = sma + 64 * ATP;       // [d][j] 64xATP
    float* Ps = sma + 2 * 64 * ATP;   // [q][*] 128xATP (Q stage, then P slabs)

    const int tid  = threadIdx.x;
    const int wid  = tid >> 5, lane = tid & 31;
    const int g    = lane >> 2, t = lane & 3;
    const int b    = blockIdx.z;
    const int h    = blockIdx.y;
    const int q0   = blockIdx.x * 128;
    const float scale = 0.125f;

    const float* Qg = Q   + ((size_t)b * SEQ + q0) * HID + h * HD;
    const float* Kg = Kin + (size_t)b * SEQ * HID + h * HD;
    const float* Vg = V   + (size_t)b * SEQ * HID + h * HD;

    // ---- stage Q (tf32) and preload fragments ----
    for (int idx = tid; idx < 128 * 16; idx += 256) {
        const int r = idx >> 4, d4 = (idx & 15) * 4;
        float4 v = *(const float4*)(Qg + (size_t)r * HID + d4);
        float* d = Ps + r * ATP + d4;
        d[0] = tf32r(v.x); d[1] = tf32r(v.y); d[2] = tf32r(v.z); d[3] = tf32r(v.w);
    }
    __syncthreads();

    uint32_t qf[8][4];
    #pragma unroll
    for (int ks = 0; ks < 8; ks++) {
        const float* qp = Ps + wid * 16 * ATP + ks * 8;
        qf[ks][0] = __float_as_uint(qp[ g      * ATP + t    ]);
        qf[ks][1] = __float_as_uint(qp[(g + 8) * ATP + t    ]);
        qf[ks][2] = __float_as_uint(qp[ g      * ATP + t + 4]);
        qf[ks][3] = __float_as_uint(qp[(g + 8) * ATP + t + 4]);
    }
    __syncthreads();

    float oacc[8][4] = {};
    float m0 = -1e30f, m1 = -1e30f, l0 = 0.0f, l1 = 0.0f;

    // staging maps
    const int jk = tid >> 2, dk = (tid & 3) * 16;    // K: [j][d]
    const int jv = tid & 63, dv = (tid >> 6) * 16;   // V: write [d][j] conflict-free

    float4 kreg[4], vreg[4];
    #pragma unroll
    for (int i = 0; i < 4; i++) {
        kreg[i] = *(const float4*)(Kg + (size_t)jk * HID + dk + 4 * i);
        vreg[i] = *(const float4*)(Vg + (size_t)jv * HID + dv + 4 * i);
    }

    for (int kv0 = 0; kv0 < SEQ; kv0 += 64) {
        __syncthreads();
        #pragma unroll
        for (int i = 0; i < 4; i++) {
            float* kd = Ks + jk * ATP + dk + 4 * i;
            kd[0] = tf32r(kreg[i].x); kd[1] = tf32r(kreg[i].y);
            kd[2] = tf32r(kreg[i].z); kd[3] = tf32r(kreg[i].w);
            const int d = dv + 4 * i;
            Vt[(d + 0) * ATP + jv] = tf32r(vreg[i].x);
            Vt[(d + 1) * ATP + jv] = tf32r(vreg[i].y);
            Vt[(d + 2) * ATP + jv] = tf32r(vreg[i].z);
            Vt[(d + 3) * ATP + jv] = tf32r(vreg[i].w);
        }
        __syncthreads();

        if (kv0 + 64 < SEQ) {
            #pragma unroll
            for (int i = 0; i < 4; i++) {
                kreg[i] = *(const float4*)(Kg + (size_t)(kv0 + 64 + jk) * HID + dk + 4 * i);
                vreg[i] = *(const float4*)(Vg + (size_t)(kv0 + 64 + jv) * HID + dv + 4 * i);
            }
        }

        // ---- S = Q K^T ----
        float s[8][4] = {};
        #pragma unroll
        for (int ks = 0; ks < 8; ks++) {
            #pragma unroll
            for (int nt = 0; nt < 8; nt++) {
                const float* bp = Ks + (nt * 8 + g) * ATP + ks * 8 + t;
                uint32_t b0 = __float_as_uint(bp[0]);
                uint32_t b1 = __float_as_uint(bp[4]);
                mma_tf32(s[nt], qf[ks], b0, b1);
            }
        }

        // ---- online softmax ----
        float rm0 = -1e30f, rm1 = -1e30f;
        #pragma unroll
        for (int nt = 0; nt < 8; nt++) {
            s[nt][0] *= scale; s[nt][1] *= scale;
            s[nt][2] *= scale; s[nt][3] *= scale;
            rm0 = fmaxf(rm0, fmaxf(s[nt][0], s[nt][1]));
            rm1 = fmaxf(rm1, fmaxf(s[nt][2], s[nt][3]));
        }
        rm0 = fmaxf(rm0, __shfl_xor_sync(0xffffffffu, rm0, 1));
        rm0 = fmaxf(rm0, __shfl_xor_sync(0xffffffffu, rm0, 2));
        rm1 = fmaxf(rm1, __shfl_xor_sync(0xffffffffu, rm1, 1));
        rm1 = fmaxf(rm1, __shfl_xor_sync(0xffffffffu, rm1, 2));

        const float nm0 = fmaxf(m0, rm0), nm1 = fmaxf(m1, rm1);
        const float a0 = __expf(m0 - nm0), a1 = __expf(m1 - nm1);
        float sum0 = 0.0f, sum1 = 0.0f;
        #pragma unroll
        for (int nt = 0; nt < 8; nt++) {
            s[nt][0] = __expf(s[nt][0] - nm0); sum0 += s[nt][0];
            s[nt][1] = __expf(s[nt][1] - nm0); sum0 += s[nt][1];
            s[nt][2] = __expf(s[nt][2] - nm1); sum1 += s[nt][2];
            s[nt][3] = __expf(s[nt][3] - nm1); sum1 += s[nt][3];
        }
        sum0 += __shfl_xor_sync(0xffffffffu, sum0, 1);
        sum0 += __shfl_xor_sync(0xffffffffu, sum0, 2);
        sum1 += __shfl_xor_sync(0xffffffffu, sum1, 1);
        sum1 += __shfl_xor_sync(0xffffffffu, sum1, 2);

        l0 = l0 * a0 + sum0; l1 = l1 * a1 + sum1;
        m0 = nm0; m1 = nm1;
        #pragma unroll
        for (int nt = 0; nt < 8; nt++) {
            oacc[nt][0] *= a0; oacc[nt][1] *= a0;
            oacc[nt][2] *= a1; oacc[nt][3] *= a1;
        }

        // ---- stage P (warp-private slab) ----
        float* Pw = Ps + wid * 16 * ATP;
        #pragma unroll
        for (int nt = 0; nt < 8; nt++) {
            Pw[ g      * ATP + nt * 8 + 2 * t    ] = tf32r(s[nt][0]);
            Pw[ g      * ATP + nt * 8 + 2 * t + 1] = tf32r(s[nt][1]);
            Pw[(g + 8) * ATP + nt * 8 + 2 * t    ] = tf32r(s[nt][2]);
            Pw[(g + 8) * ATP + nt * 8 + 2 * t + 1] = tf32r(s[nt][3]);
        }
        __syncwarp();

        // ---- O += P V ----
        #pragma unroll
        for (int ks = 0; ks < 8; ks++) {
            uint32_t af[4];
            af[0] = __float_as_uint(Pw[ g      * ATP + ks * 8 + t    ]);
            af[1] = __float_as_uint(Pw[(g + 8) * ATP + ks * 8 + t    ]);
            af[2] = __float_as_uint(Pw[ g      * ATP + ks * 8 + t + 4]);
            af[3] = __float_as_uint(Pw[(g + 8) * ATP + ks * 8 + t + 4]);
            #pragma unroll
            for (int nt = 0; nt < 8; nt++) {
                const float* bp = Vt + (nt * 8 + g) * ATP + ks * 8 + t;
                uint32_t b0 = __float_as_uint(bp[0]);
                uint32_t b1 = __float_as_uint(bp[4]);
                mma_tf32(oacc[nt], af, b0, b1);
            }
        }
    }

    // ---- epilogue ----
    const float inv0 = 1.0f / l0, inv1 = 1.0f / l1;
    float* Og = O + ((size_t)b * SEQ + q0 + wid * 16) * HID + h * HD;
    #pragma unroll
    for (int nt = 0; nt < 8; nt++) {
        const int col = nt * 8 + 2 * t;
        float2 v0 = {oacc[nt][0] * inv0, oacc[nt][1] * inv0};
        float2 v1 = {oacc[nt][2] * inv1, oacc[nt][3] * inv1};
        *(float2*)&Og[(size_t) g      * HID + col] = v0;
        *(float2*)&Og[(size_t)(g + 8) * HID + col] = v1;
    }
}

// ===========================================================================
extern "C" void kernel_launch(void* const* d_in, const int* in_sizes, int n_in,
                              void* d_out, int out_size)
{
    const float* q   = (const float*)d_in[0];   // [2,2048,1024]
    const float* Wq  = (const float*)d_in[1];   // [1024,1024]
    const float* bq  = (const float*)d_in[2];   // [1024]
    const float* Wkv = (const float*)d_in[3];   // [1024,2048]
    const float* bkv = (const float*)d_in[4];   // [2048]
    const float* Wo  = (const float*)d_in[5];   // [1024,1024]
    const float* bo  = (const float*)d_in[6];   // [1024]
    float* out = (float*)d_out;                 // [2,2048,1024]

    void *pQ, *pK, *pV, *pO;
    cudaGetSymbolAddress(&pQ, g_Q);
    cudaGetSymbolAddress(&pK, g_K);
    cudaGetSymbolAddress(&pV, g_V);
    cudaGetSymbolAddress(&pO, g_O);
    float* gQ = (float*)pQ;
    float* gK = (float*)pK;
    float* gV = (float*)pV;
    float* gO = (float*)pO;

    cudaFuncSetAttribute(gemm_tc, cudaFuncAttributeMaxDynamicSharedMemorySize,
                         GEMM_SMEM);
    cudaFuncSetAttribute(attn_tc, cudaFuncAttributeMaxDynamicSharedMemorySize,
                         ATTN_SMEM);

    dim3 blk(256);
    dim3 ggrid(HID / 128, MROWS / 128);     // (8, 32)

    // Q = q @ Wq + bq
    gemm_tc<<<ggrid, blk, GEMM_SMEM>>>(q, HID, Wq, HID, bq, gQ, HID, HID);
    // K = q @ Wkv[:, :1024] + bkv[:1024]
    gemm_tc<<<ggrid, blk, GEMM_SMEM>>>(q, HID, Wkv, 2 * HID, bkv, gK, HID, HID);
    // V = q @ Wkv[:, 1024:] + bkv[1024:]
    gemm_tc<<<ggrid, blk, GEMM_SMEM>>>(q, HID, Wkv + HID, 2 * HID, bkv + HID,
                                       gV, HID, HID);

    // attention
    dim3 agrid(SEQ / 128, NH, BATCH);       // (16, 16, 2)
    attn_tc<<<agrid, blk, ATTN_SMEM>>>(gQ, gK, gV, gO);

    // out = O @ Wo + bo
    gemm_tc<<<ggrid, blk, GEMM_SMEM>>>(gO, HID, Wo, HID, bo, out, HID, HID);
}